// round 1
// baseline (speedup 1.0000x reference)
#include <cuda_runtime.h>
#include <math.h>

// Problem constants
#define NB   16           // batch
#define CC   768          // channels
#define SS   729          // tokens (9^3)
#define MTOK (NB*SS)      // 11664 total tokens
#define HEADS 8
#define DH   96           // head dim
#define C3   (3*CC)       // 2304
#define HID  3072
#define NE   3
#define NTOT (CC*SS)      // 559872 elems per batch for LN

// ---------------- scratch (device globals; no allocation allowed) ----------------
__device__ float g_tok[(size_t)MTOK*CC];        // LN'ed tokens [M, C]
__device__ float g_qkv[(size_t)MTOK*C3];        // [M, 3C]
__device__ float g_ctx[(size_t)MTOK*CC];        // attention context [M, C]
__device__ float g_x2 [(size_t)MTOK*CC];        // x + attn_out (token layout) [M, C]
__device__ float g_H  [(size_t)NE*MTOK*HID];    // expert hidden (gathered rows)
__device__ float g_partial[16*64*2];
__device__ float g_mu[16];
__device__ float g_rinv[16];
__device__ float g_gval[MTOK];
__device__ int   g_gsel[MTOK];
__device__ float g_score[MTOK];
__device__ int   g_cnt[NE];
__device__ int   g_list[NE*MTOK];

// ---------------- init ----------------
__global__ void k_zero() {
    if (threadIdx.x < NE) g_cnt[threadIdx.x] = 0;
}

// ---------------- LayerNorm: partial sums (deterministic 2-pass) ----------------
__global__ void __launch_bounds__(256) k_ln_partial(const float* __restrict__ x) {
    int b = blockIdx.y, blk = blockIdx.x, t = threadIdx.x;
    const int chunk = NTOT / 64;   // 8748 exact
    const float* xb = x + (size_t)b*NTOT + (size_t)blk*chunk;
    float s = 0.f, s2 = 0.f;
    for (int i = t; i < chunk; i += 256) { float v = xb[i]; s += v; s2 += v*v; }
    __shared__ float sh1[256], sh2[256];
    sh1[t] = s; sh2[t] = s2; __syncthreads();
    for (int o = 128; o; o >>= 1) {
        if (t < o) { sh1[t] += sh1[t+o]; sh2[t] += sh2[t+o]; }
        __syncthreads();
    }
    if (t == 0) {
        g_partial[(b*64+blk)*2]   = sh1[0];
        g_partial[(b*64+blk)*2+1] = sh2[0];
    }
}

__global__ void k_ln_final() {
    int b = blockIdx.x, t = threadIdx.x;
    __shared__ float s1[64], s2[64];
    s1[t] = g_partial[(b*64+t)*2];
    s2[t] = g_partial[(b*64+t)*2+1];
    __syncthreads();
    for (int o = 32; o; o >>= 1) {
        if (t < o) { s1[t] += s1[t+o]; s2[t] += s2[t+o]; }
        __syncthreads();
    }
    if (t == 0) {
        float n = (float)NTOT;
        float mu = s1[0] / n;
        float var = s2[0] / n - mu*mu;
        g_mu[b] = mu;
        g_rinv[b] = rsqrtf(var + 1e-5f);
    }
}

// ---------------- LN normalize + affine + transpose [B,C,S] -> tok [B*S, C] ----------------
__global__ void __launch_bounds__(256) k_ln_t(const float* __restrict__ x,
                                              const float* __restrict__ gamma,
                                              const float* __restrict__ beta) {
    __shared__ float tile[32][33];
    int b = blockIdx.z;
    int s0 = blockIdx.x * 32, c0 = blockIdx.y * 32;
    float m = g_mu[b], r = g_rinv[b];
    int sx = threadIdx.x;
    for (int i = threadIdx.y; i < 32; i += 8) {
        int c = c0 + i, s = s0 + sx;
        float v = 0.f;
        if (s < SS) {
            size_t gi = (size_t)c*SS + s;
            v = (x[((size_t)b*CC + c)*SS + s] - m) * r * gamma[gi] + beta[gi];
        }
        tile[i][sx] = v;
    }
    __syncthreads();
    for (int i = threadIdx.y; i < 32; i += 8) {
        int s = s0 + i, c = c0 + sx;
        if (s < SS) g_tok[((size_t)(b*SS + s))*CC + c] = tile[sx][i];
    }
}

// ---------------- SGEMM cores: 64x64x16, 256 threads, 4x4 micro-tiles ----------------
#define GEMM_PROLOG(Kdim)                                     \
    __shared__ float As[16][68];                              \
    __shared__ float Bs[16][68];                              \
    int t = threadIdx.x;                                      \
    int tx = t & 15, ty = t >> 4;                             \
    int ar = t >> 2, ac = (t & 3) * 4;                        \
    int br = t >> 4, bc = (t & 15) * 4;                       \
    float acc[4][4] = {};

#define GEMM_MAIN(Kdim, Ncols)                                            \
    for (int k0 = 0; k0 < (Kdim); k0 += 16) {                             \
        float4 a4 = av ? *(const float4*)(Ap + k0) : make_float4(0,0,0,0);\
        As[ac+0][ar]=a4.x; As[ac+1][ar]=a4.y;                             \
        As[ac+2][ar]=a4.z; As[ac+3][ar]=a4.w;                             \
        float4 b4 = *(const float4*)(Bp + (size_t)k0*(Ncols));            \
        Bs[br][bc+0]=b4.x; Bs[br][bc+1]=b4.y;                             \
        Bs[br][bc+2]=b4.z; Bs[br][bc+3]=b4.w;                             \
        __syncthreads();                                                  \
        _Pragma("unroll")                                                 \
        for (int k = 0; k < 16; k++) {                                    \
            float avv[4], bvv[4];                                         \
            _Pragma("unroll")                                             \
            for (int i = 0; i < 4; i++) avv[i] = As[k][ty*4+i];           \
            _Pragma("unroll")                                             \
            for (int j = 0; j < 4; j++) bvv[j] = Bs[k][tx*4+j];           \
            _Pragma("unroll")                                             \
            for (int i = 0; i < 4; i++)                                   \
                _Pragma("unroll")                                         \
                for (int j = 0; j < 4; j++) acc[i][j] += avv[i]*bvv[j];   \
        }                                                                 \
        __syncthreads();                                                  \
    }

// GEMM 1: qkv = tok @ w_qkv   [M,768] x [768,2304]
__global__ void __launch_bounds__(256) k_gemm_qkv(const float* __restrict__ Bw) {
    int m0 = blockIdx.y * 64, n0 = blockIdx.x * 64;
    GEMM_PROLOG(CC)
    bool av = (m0 + ar) < MTOK;
    const float* Ap = g_tok + (size_t)(m0 + ar)*CC + ac;
    const float* Bp = Bw + (size_t)br*C3 + n0 + bc;
    GEMM_MAIN(CC, C3)
    #pragma unroll
    for (int i = 0; i < 4; i++) {
        int r = m0 + ty*4 + i;
        if (r < MTOK) {
            #pragma unroll
            for (int j = 0; j < 4; j++)
                g_qkv[(size_t)r*C3 + n0 + tx*4 + j] = acc[i][j];
        }
    }
}

// GEMM 2: x2 = x + ctx @ w_out   [M,768] x [768,768], residual in token layout
__global__ void __launch_bounds__(256) k_gemm_out(const float* __restrict__ Bw,
                                                  const float* __restrict__ x) {
    int m0 = blockIdx.y * 64, n0 = blockIdx.x * 64;
    GEMM_PROLOG(CC)
    bool av = (m0 + ar) < MTOK;
    const float* Ap = g_ctx + (size_t)(m0 + ar)*CC + ac;
    const float* Bp = Bw + (size_t)br*CC + n0 + bc;
    GEMM_MAIN(CC, CC)
    #pragma unroll
    for (int i = 0; i < 4; i++) {
        int r = m0 + ty*4 + i;
        if (r < MTOK) {
            int bb = r / SS, s = r - bb*SS;
            #pragma unroll
            for (int j = 0; j < 4; j++) {
                int col = n0 + tx*4 + j;
                g_x2[(size_t)r*CC + col] =
                    acc[i][j] + x[((size_t)bb*CC + col)*SS + s];
            }
        }
    }
}

// Expert GEMM 1 (gathered rows): H = gelu(x2[idx] @ w1[e] + b1[e])  [Me,768]x[768,3072]
__global__ void __launch_bounds__(256) k_gemm_e1(const float* __restrict__ w1,
                                                 const float* __restrict__ b1) {
    int e = blockIdx.z;
    int Mr = g_cnt[e];
    int m0 = blockIdx.y * 64;
    if (m0 >= Mr) return;
    int n0 = blockIdx.x * 64;
    GEMM_PROLOG(CC)
    bool av = (m0 + ar) < Mr;
    int grow = av ? g_list[e*MTOK + m0 + ar] : 0;
    const float* Ap = g_x2 + (size_t)grow*CC + ac;
    const float* Bp = w1 + (size_t)e*CC*HID + (size_t)br*HID + n0 + bc;
    GEMM_MAIN(CC, HID)
    #pragma unroll
    for (int i = 0; i < 4; i++) {
        int r = m0 + ty*4 + i;
        if (r < Mr) {
            #pragma unroll
            for (int j = 0; j < 4; j++) {
                int col = n0 + tx*4 + j;
                float hh = acc[i][j] + b1[e*HID + col];
                // exact GELU: 0.5*x*(1+erf(x/sqrt(2)))
                g_H[(size_t)(e*MTOK + r)*HID + col] =
                    0.5f * hh * (1.0f + erff(hh * 0.70710678118654752f));
            }
        }
    }
}

// Expert GEMM 2: out = x2 + score * (H @ w2[e] + b2[e]), scattered to [B,C,S]
__global__ void __launch_bounds__(256) k_gemm_e2(const float* __restrict__ w2,
                                                 const float* __restrict__ b2,
                                                 float* __restrict__ out) {
    int e = blockIdx.z;
    int Mr = g_cnt[e];
    int m0 = blockIdx.y * 64;
    if (m0 >= Mr) return;
    int n0 = blockIdx.x * 64;
    GEMM_PROLOG(HID)
    bool av = (m0 + ar) < Mr;
    const float* Ap = g_H + (size_t)(e*MTOK + m0 + ar)*HID + ac;
    const float* Bp = w2 + (size_t)e*HID*CC + (size_t)br*CC + n0 + bc;
    GEMM_MAIN(HID, CC)
    #pragma unroll
    for (int i = 0; i < 4; i++) {
        int r = m0 + ty*4 + i;
        if (r < Mr) {
            int tok = g_list[e*MTOK + r];
            int bb = tok / SS, s = tok - bb*SS;
            float sco = g_score[tok];
            #pragma unroll
            for (int j = 0; j < 4; j++) {
                int col = n0 + tx*4 + j;
                float v = g_x2[(size_t)tok*CC + col] +
                          sco * (acc[i][j] + b2[e*CC + col]);
                out[((size_t)bb*CC + col)*SS + s] = v;
            }
        }
    }
}

// ---------------- attention: 8 query rows per block, full softmax in smem ----------------
__global__ void __launch_bounds__(256) k_attn() {
    int b = blockIdx.z, h = blockIdx.y;
    int q0 = blockIdx.x * 8;
    __shared__ float qs[8][97];
    __shared__ float ks[32][97];
    __shared__ float sc[8][737];
    int t = threadIdx.x;
    // zero score tail (indices 729..736) so phase-3 unrolled loop is NaN-safe
    if (t < 64) sc[t >> 3][729 + (t & 7)] = 0.f;
    // load q rows
    for (int i = t; i < 8*96; i += 256) {
        int r = i / 96, d = i % 96;
        int qr = q0 + r;
        qs[r][d] = (qr < SS) ? g_qkv[(size_t)(b*SS + qr)*C3 + h*DH + d] : 0.f;
    }
    __syncthreads();
    // phase 1: scores = Q K^T (no 1/sqrt(d) scale, per reference)
    for (int k0 = 0; k0 < SS; k0 += 32) {
        for (int i = t; i < 32*96; i += 256) {
            int kk = i / 96, d = i % 96;
            int kr = k0 + kk;
            ks[kk][d] = (kr < SS) ? g_qkv[(size_t)(b*SS + kr)*C3 + CC + h*DH + d] : 0.f;
        }
        __syncthreads();
        int r = t >> 5, kl = t & 31;
        if (k0 + kl < SS) {
            float s = 0.f;
            #pragma unroll
            for (int d = 0; d < 96; d++) s += qs[r][d] * ks[kl][d];
            sc[r][k0 + kl] = s;
        }
        __syncthreads();
    }
    // phase 2: softmax, one warp per row
    int warp = t >> 5, lane = t & 31;
    float m = -1e30f;
    for (int k = lane; k < SS; k += 32) m = fmaxf(m, sc[warp][k]);
    #pragma unroll
    for (int o = 16; o; o >>= 1) m = fmaxf(m, __shfl_xor_sync(0xffffffffu, m, o));
    float sum = 0.f;
    for (int k = lane; k < SS; k += 32) {
        float e = __expf(sc[warp][k] - m);
        sc[warp][k] = e; sum += e;
    }
    #pragma unroll
    for (int o = 16; o; o >>= 1) sum += __shfl_xor_sync(0xffffffffu, sum, o);
    float inv = 1.f / sum;
    for (int k = lane; k < SS; k += 32) sc[warp][k] *= inv;
    __syncthreads();
    // phase 3: ctx = P @ V  (768 outputs; 3 per thread)
    float acc0 = 0.f, acc1 = 0.f, acc2 = 0.f;
    int o0 = t, o1 = t + 256, o2 = t + 512;
    int r0 = o0/96, d0 = o0%96, r1 = o1/96, d1 = o1%96, r2 = o2/96, d2 = o2%96;
    for (int k0 = 0; k0 < SS; k0 += 32) {
        for (int i = t; i < 32*96; i += 256) {
            int kk = i / 96, d = i % 96;
            int kr = k0 + kk;
            ks[kk][d] = (kr < SS) ? g_qkv[(size_t)(b*SS + kr)*C3 + 2*CC + h*DH + d] : 0.f;
        }
        __syncthreads();
        #pragma unroll 8
        for (int kk = 0; kk < 32; kk++) {
            acc0 += sc[r0][k0+kk] * ks[kk][d0];
            acc1 += sc[r1][k0+kk] * ks[kk][d1];
            acc2 += sc[r2][k0+kk] * ks[kk][d2];
        }
        __syncthreads();
    }
    int qr = q0 + r0;
    if (qr < SS) g_ctx[(size_t)(b*SS + qr)*CC + h*DH + d0] = acc0;
    qr = q0 + r1;
    if (qr < SS) g_ctx[(size_t)(b*SS + qr)*CC + h*DH + d1] = acc1;
    qr = q0 + r2;
    if (qr < SS) g_ctx[(size_t)(b*SS + qr)*CC + h*DH + d2] = acc2;
}

// ---------------- gating: one warp per token ----------------
__global__ void __launch_bounds__(256) k_gate(const float* __restrict__ wg,
                                              const float* __restrict__ bg) {
    int gw = (blockIdx.x * blockDim.x + threadIdx.x) >> 5;
    int lane = threadIdx.x & 31;
    if (gw >= MTOK) return;
    const float* row = g_x2 + (size_t)gw*CC;
    float a0 = 0.f, a1 = 0.f, a2 = 0.f;
    for (int c = lane; c < CC; c += 32) {
        float v = row[c];
        a0 += v * wg[c*3 + 0];
        a1 += v * wg[c*3 + 1];
        a2 += v * wg[c*3 + 2];
    }
    #pragma unroll
    for (int o = 16; o; o >>= 1) {
        a0 += __shfl_xor_sync(0xffffffffu, a0, o);
        a1 += __shfl_xor_sync(0xffffffffu, a1, o);
        a2 += __shfl_xor_sync(0xffffffffu, a2, o);
    }
    if (lane == 0) {
        a0 += bg[0]; a1 += bg[1]; a2 += bg[2];
        // argmax on logits (== argmax of softmax); first index on ties
        int sel = 0; float av = a0;
        if (a1 > av) { sel = 1; av = a1; }
        if (a2 > av) { sel = 2; av = a2; }
        float mx = fmaxf(a0, fmaxf(a1, a2));
        float e0 = expf(a0 - mx), e1 = expf(a1 - mx), e2 = expf(a2 - mx);
        float inv = 1.f / (e0 + e1 + e2);
        float pv = (sel == 0 ? e0 : (sel == 1 ? e1 : e2)) * inv;
        g_gval[gw] = pv;
        g_gsel[gw] = sel;
        int pos = atomicAdd(&g_cnt[sel], 1);
        g_list[sel*MTOK + pos] = gw;
    }
}

// ---------------- per-(s,e) denom over batch + final gate score ----------------
__global__ void k_score() {
    int s = blockIdx.x * blockDim.x + threadIdx.x;
    if (s >= SS) return;
    float den[3] = {0.f, 0.f, 0.f};
    for (int b = 0; b < NB; b++) {
        int r = b*SS + s;
        den[g_gsel[r]] += g_gval[r];
    }
    for (int b = 0; b < NB; b++) {
        int r = b*SS + s;
        g_score[r] = g_gval[r] * (float)NB / (den[g_gsel[r]] + 1e-6f);
    }
}

// ---------------- launch ----------------
extern "C" void kernel_launch(void* const* d_in, const int* in_sizes, int n_in,
                              void* d_out, int out_size) {
    const float* x    = (const float*)d_in[0];
    const float* lng  = (const float*)d_in[1];
    const float* lnb  = (const float*)d_in[2];
    const float* wqkv = (const float*)d_in[3];
    const float* wout = (const float*)d_in[4];
    const float* wg   = (const float*)d_in[5];
    const float* bg   = (const float*)d_in[6];
    const float* w1   = (const float*)d_in[7];
    const float* b1   = (const float*)d_in[8];
    const float* w2   = (const float*)d_in[9];
    const float* b2   = (const float*)d_in[10];
    float* out = (float*)d_out;

    k_zero<<<1, 32>>>();
    k_ln_partial<<<dim3(64, NB), 256>>>(x);
    k_ln_final<<<NB, 64>>>();
    k_ln_t<<<dim3((SS + 31)/32, CC/32, NB), dim3(32, 8)>>>(x, lng, lnb);
    k_gemm_qkv<<<dim3(C3/64, (MTOK + 63)/64), 256>>>(wqkv);
    k_attn<<<dim3((SS + 7)/8, HEADS, NB), 256>>>();
    k_gemm_out<<<dim3(CC/64, (MTOK + 63)/64), 256>>>(wout, x);
    k_gate<<<MTOK/8, 256>>>(wg, bg);
    k_score<<<(SS + 127)/128, 128>>>();
    k_gemm_e1<<<dim3(HID/64, (MTOK + 63)/64, NE), 256>>>(w1, b1);
    k_gemm_e2<<<dim3(CC/64, (MTOK + 63)/64, NE), 256>>>(w2, b2, out);
}

// round 2
// speedup vs baseline: 5.2352x; 5.2352x over previous
#include <cuda_runtime.h>
#include <math.h>
#include <stdint.h>

#define NB   16
#define CC   768
#define SS   729
#define MTOK (NB*SS)
#define HEADS 8
#define DH   96
#define C3   (3*CC)
#define HID  3072
#define NE   3
#define NTOT (CC*SS)
#define LDSP 736          // padded leading dim for S and Kt (23*32)

// ---------------- scratch ----------------
__device__ float g_tok[(size_t)MTOK*CC];
__device__ float g_qkv[(size_t)MTOK*C3];
__device__ float g_ctx[(size_t)MTOK*CC];
__device__ float g_x2 [(size_t)MTOK*CC];
__device__ float g_x2t[(size_t)MTOK*CC];
__device__ float g_H  [(size_t)NE*MTOK*HID];
__device__ float g_S  [(size_t)NB*HEADS*SS*LDSP];
__device__ float g_kt [(size_t)NB*HEADS*DH*LDSP + 256];
__device__ float c_wqkv[(size_t)CC*C3];
__device__ float c_wout[(size_t)CC*CC];
__device__ float c_w1[(size_t)NE*CC*HID];
__device__ float c_w2[(size_t)NE*HID*CC];
__device__ float g_partial[16*64*2];
__device__ float g_mu[16];
__device__ float g_rinv[16];
__device__ float g_gval[MTOK];
__device__ int   g_gsel[MTOK];
__device__ float g_score[MTOK];
__device__ int   g_cnt[NE];
__device__ int   g_list[NE*MTOK];

// ---------------- helpers ----------------
__device__ __forceinline__ uint32_t f2tf(float f){
    uint32_t r; asm("cvt.rna.tf32.f32 %0, %1;" : "=r"(r) : "f"(f)); return r;
}
__device__ __forceinline__ float tfr(float f){ return __uint_as_float(f2tf(f)); }

__device__ __forceinline__ void mma8(float c[4], const uint32_t a[4], const uint32_t b[2]){
    asm volatile("mma.sync.aligned.m16n8k8.row.col.f32.tf32.tf32.f32 "
        "{%0,%1,%2,%3}, {%4,%5,%6,%7}, {%8,%9}, {%0,%1,%2,%3};"
        : "+f"(c[0]), "+f"(c[1]), "+f"(c[2]), "+f"(c[3])
        : "r"(a[0]), "r"(a[1]), "r"(a[2]), "r"(a[3]), "r"(b[0]), "r"(b[1]));
}
__device__ __forceinline__ void cpa(uint32_t dst, const float* src, bool p){
    int sz = p ? 16 : 0;
    asm volatile("cp.async.ca.shared.global [%0], [%1], 16, %2;\n"
                 :: "r"(dst), "l"(src), "r"(sz));
}
__device__ __forceinline__ void cpcommit(){ asm volatile("cp.async.commit_group;\n"); }
template<int N> __device__ __forceinline__ void cpwait(){
    asm volatile("cp.async.wait_group %0;\n" :: "n"(N));
}

// ---------------- init ----------------
__global__ void k_zero(){ if (threadIdx.x < NE) g_cnt[threadIdx.x] = 0; }

__global__ void k_cvtw(const float* __restrict__ s, float* __restrict__ d, int n){
    int i = blockIdx.x*256 + threadIdx.x;
    if (i < n) d[i] = tfr(s[i]);
}

// ---------------- LayerNorm ----------------
__global__ void __launch_bounds__(256) k_ln_partial(const float* __restrict__ x){
    int b = blockIdx.y, blk = blockIdx.x, t = threadIdx.x;
    const int chunk = NTOT / 64;
    const float* xb = x + (size_t)b*NTOT + (size_t)blk*chunk;
    float s = 0.f, s2 = 0.f;
    for (int i = t; i < chunk; i += 256){ float v = xb[i]; s += v; s2 += v*v; }
    __shared__ float sh1[256], sh2[256];
    sh1[t]=s; sh2[t]=s2; __syncthreads();
    for (int o=128;o;o>>=1){ if(t<o){sh1[t]+=sh1[t+o]; sh2[t]+=sh2[t+o];} __syncthreads(); }
    if (!t){ g_partial[(b*64+blk)*2]=sh1[0]; g_partial[(b*64+blk)*2+1]=sh2[0]; }
}
__global__ void k_ln_final(){
    int b = blockIdx.x, t = threadIdx.x;
    __shared__ float s1[64], s2[64];
    s1[t]=g_partial[(b*64+t)*2]; s2[t]=g_partial[(b*64+t)*2+1]; __syncthreads();
    for (int o=32;o;o>>=1){ if(t<o){s1[t]+=s1[t+o]; s2[t]+=s2[t+o];} __syncthreads(); }
    if (!t){
        float n=(float)NTOT, mu=s1[0]/n, var=s2[0]/n-mu*mu;
        g_mu[b]=mu; g_rinv[b]=rsqrtf(var+1e-5f);
    }
}
__global__ void __launch_bounds__(256) k_ln_t(const float* __restrict__ x,
                                              const float* __restrict__ gamma,
                                              const float* __restrict__ beta){
    __shared__ float tile[32][33];
    int b=blockIdx.z, s0=blockIdx.x*32, c0=blockIdx.y*32;
    float m=g_mu[b], r=g_rinv[b];
    int sx=threadIdx.x;
    for (int i=threadIdx.y;i<32;i+=8){
        int c=c0+i, s=s0+sx; float v=0.f;
        if (s<SS){ size_t gi=(size_t)c*SS+s;
            v = (x[((size_t)b*CC+c)*SS+s]-m)*r*gamma[gi]+beta[gi]; }
        tile[i][sx]=v;
    }
    __syncthreads();
    for (int i=threadIdx.y;i<32;i+=8){
        int s=s0+i, c=c0+sx;
        if (s<SS) g_tok[((size_t)(b*SS+s))*CC+c] = tfr(tile[sx][i]);
    }
}

// ---------------- K transpose: g_kt[bh][d][s] ----------------
__global__ void k_kt(){
    __shared__ float tile[32][33];
    int bh=blockIdx.z; int b=bh>>3, h=bh&7;
    int s0=blockIdx.x*32, d0=blockIdx.y*32;
    int tx=threadIdx.x;
    for (int i=threadIdx.y;i<32;i+=8){
        int s=s0+i, d=d0+tx;
        tile[i][tx] = (s<SS) ? g_qkv[(size_t)(b*SS+s)*C3 + CC + h*DH + d] : 0.f;
    }
    __syncthreads();
    for (int i=threadIdx.y;i<32;i+=8){
        int d=d0+i, s=s0+tx;
        g_kt[((size_t)bh*DH + d)*LDSP + s] = tile[tx][i];
    }
}

// ---------------- softmax rows of S (and tf32-round P, zero the pad) ----------------
__global__ void __launch_bounds__(256) k_softmax(){
    int row = blockIdx.x*8 + (threadIdx.x>>5);
    int lane = threadIdx.x & 31;
    float* p = g_S + (size_t)row*LDSP;
    float m = -1e30f;
    for (int k=lane;k<SS;k+=32) m = fmaxf(m, p[k]);
    #pragma unroll
    for (int o=16;o;o>>=1) m = fmaxf(m, __shfl_xor_sync(0xffffffffu, m, o));
    float s = 0.f;
    for (int k=lane;k<SS;k+=32) s += __expf(p[k]-m);
    #pragma unroll
    for (int o=16;o;o>>=1) s += __shfl_xor_sync(0xffffffffu, s, o);
    float inv = 1.f/s;
    for (int k=lane;k<SS;k+=32) p[k] = tfr(__expf(p[k]-m)*inv);
    if (lane < LDSP-SS) p[SS+lane] = 0.f;
}

// ---------------- gating ----------------
__global__ void __launch_bounds__(256) k_gate(const float* __restrict__ wg,
                                              const float* __restrict__ bg){
    int gw = (blockIdx.x*blockDim.x + threadIdx.x) >> 5;
    int lane = threadIdx.x & 31;
    if (gw >= MTOK) return;
    const float* row = g_x2 + (size_t)gw*CC;
    float a0=0.f,a1=0.f,a2=0.f;
    for (int c=lane;c<CC;c+=32){
        float v=row[c];
        a0 += v*wg[c*3+0]; a1 += v*wg[c*3+1]; a2 += v*wg[c*3+2];
    }
    #pragma unroll
    for (int o=16;o;o>>=1){
        a0 += __shfl_xor_sync(0xffffffffu,a0,o);
        a1 += __shfl_xor_sync(0xffffffffu,a1,o);
        a2 += __shfl_xor_sync(0xffffffffu,a2,o);
    }
    if (!lane){
        a0+=bg[0]; a1+=bg[1]; a2+=bg[2];
        int sel=0; float av=a0;
        if (a1>av){sel=1;av=a1;}
        if (a2>av){sel=2;av=a2;}
        float mx=fmaxf(a0,fmaxf(a1,a2));
        float e0=expf(a0-mx), e1=expf(a1-mx), e2=expf(a2-mx);
        float inv=1.f/(e0+e1+e2);
        float pv=(sel==0?e0:(sel==1?e1:e2))*inv;
        g_gval[gw]=pv; g_gsel[gw]=sel;
        int pos=atomicAdd(&g_cnt[sel],1);
        g_list[sel*MTOK+pos]=gw;
    }
}
__global__ void k_score(){
    int s = blockIdx.x*blockDim.x + threadIdx.x;
    if (s >= SS) return;
    float den[3]={0.f,0.f,0.f};
    for (int b=0;b<NB;b++){ int r=b*SS+s; den[g_gsel[r]] += g_gval[r]; }
    for (int b=0;b<NB;b++){ int r=b*SS+s;
        g_score[r] = g_gval[r]*(float)NB/(den[g_gsel[r]]+1e-6f); }
}

// ---------------- tensor-core GEMM, 128x128x32 tile, 4 warps, tf32 mma ----------------
// MODE 0: qkv = tok @ wqkv            1: x2 = ctx @ wout + x
//      2: H = gelu(x2t[list] @ w1+b1) 3: out = x2 + score*(H @ w2 + b2)
//      4: S = Q @ Kt (per b,h)        5: ctx = P @ V (per b,h)
template<int MODE>
__global__ void __launch_bounds__(128) k_mma(const float* __restrict__ aux0,
                                             float* __restrict__ outp){
    extern __shared__ uint32_t smraw[];
    const int t  = threadIdx.x;
    const int n0 = blockIdx.x*128;
    const int m0 = blockIdx.y*128;
    const int z  = blockIdx.z;

    constexpr int K = (MODE==3) ? HID : (MODE==4) ? DH : (MODE==5) ? LDSP : CC;
    constexpr int NT = K/32;

    int M; const float* pa; const float* pb; size_t lda, ldb;
    const int* list = nullptr; const float* bias = nullptr;
    int b=0, h=0, e=0;
    if (MODE==0){ M=MTOK; pa=g_tok; lda=CC; pb=c_wqkv; ldb=C3; }
    if (MODE==1){ M=MTOK; pa=g_ctx; lda=CC; pb=c_wout; ldb=CC; }
    if (MODE==2){ e=z; M=g_cnt[e]; pa=g_x2t; lda=CC;
                  pb=c_w1+(size_t)e*CC*HID; ldb=HID;
                  list=g_list+e*MTOK; bias=aux0+(size_t)e*HID; }
    if (MODE==3){ e=z; M=g_cnt[e]; pa=g_H+(size_t)e*MTOK*HID; lda=HID;
                  pb=c_w2+(size_t)e*HID*CC; ldb=CC;
                  list=g_list+e*MTOK; bias=aux0+(size_t)e*CC; }
    if (MODE==4){ b=z>>3; h=z&7; M=SS;
                  pa=g_qkv+(size_t)b*SS*C3 + h*DH; lda=C3;
                  pb=g_kt+(size_t)z*DH*LDSP; ldb=LDSP; }
    if (MODE==5){ b=z>>3; h=z&7; M=SS;
                  pa=g_S+(size_t)z*SS*LDSP; lda=LDSP;
                  pb=g_qkv+(size_t)b*SS*C3 + 2*CC + h*DH; ldb=C3; }
    if (m0 >= M) return;

    // ---- A/B global pointers per thread ----
    const int c8  = t & 7;           // A float4 column
    const int r16 = t >> 3;          // A row within 16-row slab
    const int kb  = t >> 5;          // B k-row within 4
    const int n4  = (t & 31) * 4;    // B column

    const float* arow[8]; bool aok[8];
    #pragma unroll
    for (int i=0;i<8;i++){
        int r = m0 + i*16 + r16;
        bool ok = r < M;
        int rr = ok ? r : 0;
        if (MODE==2){ int gi = ok ? list[r] : 0; arow[i] = pa + (size_t)gi*lda + c8*4; }
        else          arow[i] = pa + (size_t)rr*lda + c8*4;
        aok[i] = ok;
    }
    const float* pbT = pb + (size_t)kb*ldb + n0 + n4;
    const int nbound = (MODE==4) ? LDSP : (MODE==5) ? DH : (1<<30);
    const bool nok = (n0 + n4) < nbound;
    const int kreal = (MODE==5) ? SS : (1<<30);

    uint32_t sb = (uint32_t)__cvta_generic_to_shared(smraw);
    uint32_t adst[8], bdst[8];
    #pragma unroll
    for (int i=0;i<8;i++){
        int row = i*16 + r16, k0 = c8*4;
        adst[i] = sb + 4u*(uint32_t)((row<<5) | (k0 ^ ((row<<2)&31)));
    }
    #pragma unroll
    for (int i=0;i<8;i++){
        int kr = i*4 + kb;
        bdst[i] = sb + 4u*(uint32_t)(4096 + ((kr<<7) | (n4 ^ ((kr&3)<<3))));
    }

    auto issue = [&](int kt, int bufsel){
        uint32_t off = (uint32_t)bufsel * 32768u;
        #pragma unroll
        for (int i=0;i<8;i++) cpa(adst[i]+off, arow[i]+kt, aok[i]);
        #pragma unroll
        for (int i=0;i<8;i++){
            bool p = nok && (kt + i*4 + kb) < kreal;
            const float* s = p ? (pbT + (size_t)(kt + i*4)*ldb) : pb;
            cpa(bdst[i]+off, s, p);
        }
        cpcommit();
    };

    const int w = t>>5, wm = w>>1, wn = w&1;
    const int lane = t&31, lg = lane>>2, lq = lane&3;
    float acc[4][8][4] = {};

    issue(0, 0);
    #pragma unroll 1
    for (int it=0; it<NT; it++){
        if (it+1 < NT) issue((it+1)*32, (it+1)&1);
        else cpcommit();
        cpwait<1>();
        __syncthreads();
        const uint32_t* As = smraw + (it&1)*8192;
        const uint32_t* Bs = As + 4096;
        #pragma unroll
        for (int ks=0; ks<4; ks++){
            const int kk = ks*8;
            uint32_t af[4][4], bf[8][2];
            #pragma unroll
            for (int mt=0;mt<4;mt++){
                int m = wm*64 + mt*16 + lg;
                int k = kk + lq;
                af[mt][0] = As[( m    <<5) | ( k    ^ (( m   <<2)&31))];
                af[mt][1] = As[((m+8) <<5) | ( k    ^ (((m+8)<<2)&31))];
                af[mt][2] = As[( m    <<5) | ((k+4) ^ (( m   <<2)&31))];
                af[mt][3] = As[((m+8) <<5) | ((k+4) ^ (((m+8)<<2)&31))];
            }
            #pragma unroll
            for (int nt=0;nt<8;nt++){
                int n = wn*64 + nt*8 + lg;
                int k = kk + lq;
                bf[nt][0] = Bs[( k    <<7) | (n ^ (( k   &3)<<3))];
                bf[nt][1] = Bs[((k+4) <<7) | (n ^ (((k+4)&3)<<3))];
            }
            #pragma unroll
            for (int mt=0;mt<4;mt++)
                #pragma unroll
                for (int nt=0;nt<8;nt++) mma8(acc[mt][nt], af[mt], bf[nt]);
        }
        __syncthreads();
    }

    // ---- epilogue ----
    #pragma unroll
    for (int ri=0; ri<8; ri++){
        const int mt = ri>>1, up = ri&1;
        const int r = m0 + wm*64 + mt*16 + up*8 + lg;
        if (r >= M) continue;
        int bb=0, s=0, tok=0; float sco=0.f;
        const float* x2row = nullptr;
        if (MODE==1){ bb = r/SS; s = r - bb*SS; }
        if (MODE==3){ tok = list[r]; bb = tok/SS; s = tok - bb*SS;
                      sco = g_score[tok]; x2row = g_x2 + (size_t)tok*CC; }
        #pragma unroll
        for (int nt=0;nt<8;nt++){
            #pragma unroll
            for (int j=0;j<2;j++){
                const int col = n0 + wn*64 + nt*8 + lq*2 + j;
                const float v = acc[mt][nt][up*2 + j];
                if (MODE==0){
                    g_qkv[(size_t)r*C3 + col] = tfr(v);
                } else if (MODE==1){
                    float x2 = v + aux0[((size_t)bb*CC + col)*SS + s];
                    g_x2 [(size_t)r*CC + col] = x2;
                    g_x2t[(size_t)r*CC + col] = tfr(x2);
                } else if (MODE==2){
                    float hh = v + bias[col];
                    float g = 0.5f*hh*(1.0f + erff(hh*0.70710678118654752f));
                    g_H[(size_t)(e*MTOK + r)*HID + col] = tfr(g);
                } else if (MODE==3){
                    outp[((size_t)bb*CC + col)*SS + s] =
                        x2row[col] + sco*(v + bias[col]);
                } else if (MODE==4){
                    if (col < SS) g_S[((size_t)z*SS + r)*LDSP + col] = v;
                } else { // 5
                    if (col < DH)
                        g_ctx[((size_t)b*SS + r)*CC + h*DH + col] = tfr(v);
                }
            }
        }
    }
}

// ---------------- launch ----------------
extern "C" void kernel_launch(void* const* d_in, const int* in_sizes, int n_in,
                              void* d_out, int out_size){
    const float* x    = (const float*)d_in[0];
    const float* lng  = (const float*)d_in[1];
    const float* lnb  = (const float*)d_in[2];
    const float* wqkv = (const float*)d_in[3];
    const float* wout = (const float*)d_in[4];
    const float* wg   = (const float*)d_in[5];
    const float* bg   = (const float*)d_in[6];
    const float* w1   = (const float*)d_in[7];
    const float* b1   = (const float*)d_in[8];
    const float* w2   = (const float*)d_in[9];
    const float* b2   = (const float*)d_in[10];
    float* out = (float*)d_out;

    const int SMB = 65536;
    cudaFuncSetAttribute(k_mma<0>, cudaFuncAttributeMaxDynamicSharedMemorySize, SMB);
    cudaFuncSetAttribute(k_mma<1>, cudaFuncAttributeMaxDynamicSharedMemorySize, SMB);
    cudaFuncSetAttribute(k_mma<2>, cudaFuncAttributeMaxDynamicSharedMemorySize, SMB);
    cudaFuncSetAttribute(k_mma<3>, cudaFuncAttributeMaxDynamicSharedMemorySize, SMB);
    cudaFuncSetAttribute(k_mma<4>, cudaFuncAttributeMaxDynamicSharedMemorySize, SMB);
    cudaFuncSetAttribute(k_mma<5>, cudaFuncAttributeMaxDynamicSharedMemorySize, SMB);

    float* cwqkv; cudaGetSymbolAddress((void**)&cwqkv, c_wqkv);
    float* cwout; cudaGetSymbolAddress((void**)&cwout, c_wout);
    float* cw1;   cudaGetSymbolAddress((void**)&cw1, c_w1);
    float* cw2;   cudaGetSymbolAddress((void**)&cw2, c_w2);

    k_zero<<<1, 32>>>();
    k_cvtw<<<(CC*C3+255)/256, 256>>>(wqkv, cwqkv, CC*C3);
    k_cvtw<<<(CC*CC+255)/256, 256>>>(wout, cwout, CC*CC);
    k_cvtw<<<(NE*CC*HID+255)/256, 256>>>(w1, cw1, NE*CC*HID);
    k_cvtw<<<(NE*HID*CC+255)/256, 256>>>(w2, cw2, NE*HID*CC);

    k_ln_partial<<<dim3(64, NB), 256>>>(x);
    k_ln_final<<<NB, 64>>>();
    k_ln_t<<<dim3((SS+31)/32, CC/32, NB), dim3(32, 8)>>>(x, lng, lnb);

    k_mma<0><<<dim3(C3/128, (MTOK+127)/128, 1), 128, SMB>>>(nullptr, nullptr);
    k_kt<<<dim3(LDSP/32, DH/32, NB*HEADS), dim3(32, 8)>>>();
    k_mma<4><<<dim3(6, 6, NB*HEADS), 128, SMB>>>(nullptr, nullptr);
    k_softmax<<<NB*HEADS*SS/8, 256>>>();
    k_mma<5><<<dim3(1, 6, NB*HEADS), 128, SMB>>>(nullptr, nullptr);
    k_mma<1><<<dim3(CC/128, (MTOK+127)/128, 1), 128, SMB>>>(x, nullptr);

    k_gate<<<MTOK/8, 256>>>(wg, bg);
    k_score<<<(SS+127)/128, 128>>>();
    k_mma<2><<<dim3(HID/128, (MTOK+127)/128, NE), 128, SMB>>>(b1, nullptr);
    k_mma<3><<<dim3(CC/128, (MTOK+127)/128, NE), 128, SMB>>>(b2, out);
}